// round 8
// baseline (speedup 1.0000x reference)
#include <cuda_runtime.h>

// out[row, :] = W[ids[row], :]
// W: [50257, 1024] fp32, ids: [32768] int32, out: [32768, 1024] fp32
// Best-measured config (R4): 4 rows per CTA, 256 threads, 4 independent
// 128-bit gathers per thread. Single change vs R4: output stores use
// write-through (__stwt) so output lines stay CLEAN in L2 — no deferred
// writeback bursts at eviction, smoother read/write interleave at the
// memory controller.
__global__ void __launch_bounds__(256)
embed_gather_kernel(const float4* __restrict__ w,
                    const int* __restrict__ ids,
                    float4* __restrict__ out)
{
    const int row0 = blockIdx.x * 4;
    const int t = threadIdx.x;

    const long long id0 = (long long)ids[row0 + 0];
    const long long id1 = (long long)ids[row0 + 1];
    const long long id2 = (long long)ids[row0 + 2];
    const long long id3 = (long long)ids[row0 + 3];

    // 4 independent gathers — all issued before any consumer.
    const float4 v0 = __ldg(w + id0 * 256 + t);
    const float4 v1 = __ldg(w + id1 * 256 + t);
    const float4 v2 = __ldg(w + id2 * 256 + t);
    const float4 v3 = __ldg(w + id3 * 256 + t);

    float4* dst = out + (long long)row0 * 256 + t;
    __stwt(dst + 0 * 256, v0);   // write-through: clean in L2, no wb bursts
    __stwt(dst + 1 * 256, v1);
    __stwt(dst + 2 * 256, v2);
    __stwt(dst + 3 * 256, v3);
}

extern "C" void kernel_launch(void* const* d_in, const int* in_sizes, int n_in,
                              void* d_out, int out_size)
{
    // Resolve input order by element count: weight = 50257*1024, ids = 32768.
    int wi = 0, ii = 1;
    if (in_sizes[0] < in_sizes[1]) { wi = 1; ii = 0; }

    const float4* w   = (const float4*)d_in[wi];
    const int*    ids = (const int*)d_in[ii];
    const int n_rows  = in_sizes[ii];              // 32768, divisible by 4

    float4* out = (float4*)d_out;
    embed_gather_kernel<<<n_rows / 4, 256>>>(w, ids, out);
}

// round 9
// speedup vs baseline: 1.0378x; 1.0378x over previous
#include <cuda_runtime.h>

// out[row, :] = W[ids[row], :]
// W: [50257, 1024] fp32, ids: [32768] int32, out: [32768, 1024] fp32
// Scaled R4 (best measured): 8 rows per CTA, 256 threads, 8 independent
// 128-bit gathers per thread (8x outstanding reads on the proven-fastest
// access width), evict-first streaming stores.
__global__ void __launch_bounds__(256)
embed_gather_kernel(const float4* __restrict__ w,
                    const int* __restrict__ ids,
                    float4* __restrict__ out)
{
    const int row0 = blockIdx.x * 8;
    const int t = threadIdx.x;

    long long id[8];
    #pragma unroll
    for (int i = 0; i < 8; ++i)
        id[i] = (long long)ids[row0 + i];   // broadcast loads

    // 8 independent gathers — all issued before any consumer.
    float4 v[8];
    #pragma unroll
    for (int i = 0; i < 8; ++i)
        v[i] = __ldg(w + id[i] * 256 + t);

    float4* dst = out + (long long)row0 * 256 + t;
    #pragma unroll
    for (int i = 0; i < 8; ++i)
        __stcs(dst + i * 256, v[i]);        // evict-first streaming store
}

extern "C" void kernel_launch(void* const* d_in, const int* in_sizes, int n_in,
                              void* d_out, int out_size)
{
    // Resolve input order by element count: weight = 50257*1024, ids = 32768.
    int wi = 0, ii = 1;
    if (in_sizes[0] < in_sizes[1]) { wi = 1; ii = 0; }

    const float4* w   = (const float4*)d_in[wi];
    const int*    ids = (const int*)d_in[ii];
    const int n_rows  = in_sizes[ii];              // 32768, divisible by 8

    float4* out = (float4*)d_out;
    embed_gather_kernel<<<n_rows / 8, 256>>>(w, ids, out);
}